// round 16
// baseline (speedup 1.0000x reference)
#include <cuda_runtime.h>
#include <cstdint>
#include <math.h>

using u64 = unsigned long long;

// Problem constants
constexpr int S = 4;
constexpr int T = 512;
constexpr int B = 16;
constexpr int D = 512;

constexpr int CPB     = 37;            // block slots per batch
constexpr int NBLOCKS = CPB * B;       // 592 = 148 SMs * occ 4, one packed wave
constexpr int NACC    = 16;            // 16 squared distances (sp*4+sg)
constexpr int NLOC    = 4;             // per-thread accs (1 sp x 4 sg)

// Deterministic scratch
__device__ float g_part[B][CPB][NACC];
__device__ int   g_done = 0;

struct U64x4 { u64 a, b, c, d; };

__device__ __forceinline__ void fma2(u64& acc, u64 a, u64 b) {
    asm("fma.rn.f32x2 %0, %1, %2, %0;" : "+l"(acc) : "l"(a), "l"(b));
}
__device__ __forceinline__ u64 fma2v(u64 a, u64 b, u64 c) {   // a*b + c
    u64 r;
    asm("fma.rn.f32x2 %0, %1, %2, %3;" : "=l"(r) : "l"(a), "l"(b), "l"(c));
    return r;
}
__device__ __forceinline__ float unpack_sum(u64 v) {
    float lo, hi;
    asm("mov.b64 {%0, %1}, %2;" : "=f"(lo), "=f"(hi) : "l"(v));
    return lo + hi;
}

// 256-bit loads with L2 eviction priority (sm_103a requires v4.b64 for hints).
// preds: streamed once per replay -> evict_first (don't pollute L2)
__device__ __forceinline__ U64x4 ld_stream256(const void* p) {
    U64x4 v;
    asm("ld.global.nc.L2::evict_first.v4.b64 {%0,%1,%2,%3}, [%4];"
        : "=l"(v.a), "=l"(v.b), "=l"(v.c), "=l"(v.d) : "l"(p));
    return v;
}
// gts: 67 MB, fits in L2 -> evict_last (pin across graph replays)
__device__ __forceinline__ U64x4 ld_pin256(const void* p) {
    U64x4 v;
    asm("ld.global.nc.L2::evict_last.v4.b64 {%0,%1,%2,%3}, [%4];"
        : "=l"(v.a), "=l"(v.b), "=l"(v.c), "=l"(v.d) : "l"(p));
    return v;
}

// ---------------------------------------------------------------------------
// Occ-4 fused kernel: LDG.256 + quarter-split accumulators + fma-neg fusion
// + pointer-bump + L2 eviction split (preds stream / gts pinned).
// Block (cx, b): batch b, rows t = cx + k*CPB (13 or 14 rows).
// Thread layout: lane64 = tid & 63 spans D via 32B chunks (64*32B = 2048B);
// quarter q = tid>>6 computes ONLY pred-source sp=q (4 packed accumulators).
// Per iter: 1 p-load + 4 g-loads (g shared across quarters -> L1 merge),
// 16x d=fma2(g,-1,p) + 16x acc=fma2(d,d,acc).
// ---------------------------------------------------------------------------
__global__ __launch_bounds__(256, 4) void minloss_fused(
    const float* __restrict__ preds,   // [S, T, B, D]
    const float* __restrict__ gts,     // [S, B, T, D]
    float* __restrict__ out)
{
    const int b   = blockIdx.y;
    const int cx  = blockIdx.x;
    const int tid = threadIdx.x;
    const int lane64 = tid & 63;       // 32B chunk within the 2048B row
    const int q      = tid >> 6;       // quarter = my pred source sp

    // Byte-granular pointer bumping
    const char* pp = (const char*)preds
        + ((size_t)(q * T + cx) * B + b) * (D * 4) + lane64 * 32;
    const char* gp[4];
#pragma unroll
    for (int s = 0; s < 4; ++s)
        gp[s] = (const char*)gts
              + ((size_t)(s * B + b) * T + cx) * (D * 4) + lane64 * 32;

    constexpr size_t PSTEP = (size_t)CPB * B * D * 4;   // bytes per t-step (preds)
    constexpr size_t GSTEP = (size_t)CPB * D * 4;       // bytes per t-step (gts)
    constexpr u64 NEG1 = 0xBF800000BF800000ull;         // (-1.f, -1.f)

    u64 acc[NLOC];
#pragma unroll
    for (int i = 0; i < NLOC; ++i) acc[i] = 0ull;

    const int niter = (T - cx + CPB - 1) / CPB;         // 13 or 14

    for (int it = 0; it < niter; ++it) {
        U64x4 pr = ld_stream256(pp);
        U64x4 gr[4];
#pragma unroll
        for (int s = 0; s < 4; ++s) gr[s] = ld_pin256(gp[s]);

#pragma unroll
        for (int sg = 0; sg < 4; ++sg) {
            u64 d0 = fma2v(gr[sg].a, NEG1, pr.a);       // p - g
            fma2(acc[sg], d0, d0);
            u64 d1 = fma2v(gr[sg].b, NEG1, pr.b);
            fma2(acc[sg], d1, d1);
            u64 d2 = fma2v(gr[sg].c, NEG1, pr.c);
            fma2(acc[sg], d2, d2);
            u64 d3 = fma2v(gr[sg].d, NEG1, pr.d);
            fma2(acc[sg], d3, d3);
        }

        pp += PSTEP;
#pragma unroll
        for (int s = 0; s < 4; ++s) gp[s] += GSTEP;
    }

    // ---------------- block reduction ----------------
    float vals[NLOC];
#pragma unroll
    for (int i = 0; i < NLOC; ++i) {
        vals[i] = unpack_sum(acc[i]);
#pragma unroll
        for (int off = 16; off > 0; off >>= 1)
            vals[i] += __shfl_down_sync(0xffffffffu, vals[i], off);
    }

    __shared__ float sacc[8][NLOC];
    const int warp = tid >> 5;
    const int lane = tid & 31;
    if (lane == 0) {
#pragma unroll
        for (int i = 0; i < NLOC; ++i) sacc[warp][i] = vals[i];
    }
    __syncthreads();

    // acc index i (0..15): sp = i>>2, sg = i&3; contributed by warps {2sp, 2sp+1}.
    if (tid < NACC) {
        const int sp = tid >> 2, sg = tid & 3;
        g_part[b][cx][tid] = sacc[2 * sp][sg] + sacc[2 * sp + 1][sg];
    }

    // ---- last-block ticket ----
    __threadfence();
    __syncthreads();
    __shared__ int s_last;
    if (tid == 0) {
        int ticket = atomicAdd(&g_done, 1);
        s_last = (ticket == NBLOCKS - 1);
    }
    __syncthreads();
    if (!s_last) return;

    // ================= Phase B (last block) =================
    __threadfence();                                    // acquire

    __shared__ float s_final[B][NACC];
#pragma unroll
    for (int k = 0; k < 2; ++k) {
        const int bb = warp * 2 + k;
        if (lane < NACC) {
            float a = 0.0f;
#pragma unroll
            for (int cc = 0; cc < CPB; ++cc)
                a += __ldcg(&g_part[bb][cc][lane]);     // L2, bypass stale L1
            s_final[bb][lane] = a;
        }
    }
    __syncthreads();

    __shared__ float batch_total[B];
    if (tid < B) {
        const float* a = s_final[tid];
        float dist[16];
#pragma unroll
        for (int i = 0; i < 16; ++i)
            dist[i] = sqrtf(fmaxf(a[i], 0.0f));         // d2 >= 0 by construction

        const float INF = __int_as_float(0x7f800000);
        float total = 0.0f;
#pragma unroll
        for (int it = 0; it < 4; ++it) {
            int   m    = 0;
            float best = dist[0];
#pragma unroll
            for (int k = 1; k < 16; ++k)
                if (dist[k] < best) { best = dist[k]; m = k; }   // first occurrence
            total += best;
            const int r = m >> 2, cc = m & 3;
#pragma unroll
            for (int k = 0; k < 4; ++k) {
                dist[r * 4 + k]  = INF;
                dist[k * 4 + cc] = INF;
            }
        }
        batch_total[tid] = total;
    }
    __syncthreads();

    if (tid == 0) {
        float s = 0.0f;
#pragma unroll
        for (int bb = 0; bb < B; ++bb) s += batch_total[bb];
        out[0] = s;
        g_done = 0;                                     // reset for next graph replay
    }
}

extern "C" void kernel_launch(void* const* d_in, const int* in_sizes, int n_in,
                              void* d_out, int out_size)
{
    const float* preds = (const float*)d_in[0];  // [4, 512, 16, 512]
    const float* gts   = (const float*)d_in[1];  // [4, 16, 512, 512]
    float* out = (float*)d_out;

    dim3 grid(CPB, B);                           // (37, 16) = 592 blocks, one wave
    minloss_fused<<<grid, 256>>>(preds, gts, out);
}